// round 1
// baseline (speedup 1.0000x reference)
#include <cuda_runtime.h>

#define B_CONST 8192
#define D_CONST 4096
#define MARGIN 0.5f
#define THREADS 256

__global__ void zero_out_kernel(float* out) {
    out[0] = 0.0f;
}

__global__ __launch_bounds__(THREADS) void triplet_loss_kernel(
    const float* __restrict__ feats,
    const float* __restrict__ label,
    const int* __restrict__ idx1,
    const int* __restrict__ idx2,
    float* __restrict__ out)
{
    const int b = blockIdx.x;
    const int tid = threadIdx.x;

    const int i1 = idx1[b];
    const int i2 = idx2[b];

    const float4* __restrict__ a  = (const float4*)(feats + (long long)b  * D_CONST);
    const float4* __restrict__ t1 = (const float4*)(feats + (long long)i1 * D_CONST);
    const float4* __restrict__ t2 = (const float4*)(feats + (long long)i2 * D_CONST);

    float s_abs1 = 0.f, s_abs2 = 0.f, s_sq1 = 0.f, s_sq2 = 0.f;

    const int NV = D_CONST / 4;  // 1024 float4s per row
    #pragma unroll
    for (int i = tid; i < NV; i += THREADS) {
        float4 av = __ldg(a + i);
        float4 v1 = __ldg(t1 + i);
        float4 v2 = __ldg(t2 + i);

        float d;
        d = av.x - v1.x; s_abs1 += fabsf(d); s_sq1 = fmaf(d, d, s_sq1);
        d = av.y - v1.y; s_abs1 += fabsf(d); s_sq1 = fmaf(d, d, s_sq1);
        d = av.z - v1.z; s_abs1 += fabsf(d); s_sq1 = fmaf(d, d, s_sq1);
        d = av.w - v1.w; s_abs1 += fabsf(d); s_sq1 = fmaf(d, d, s_sq1);

        d = av.x - v2.x; s_abs2 += fabsf(d); s_sq2 = fmaf(d, d, s_sq2);
        d = av.y - v2.y; s_abs2 += fabsf(d); s_sq2 = fmaf(d, d, s_sq2);
        d = av.z - v2.z; s_abs2 += fabsf(d); s_sq2 = fmaf(d, d, s_sq2);
        d = av.w - v2.w; s_abs2 += fabsf(d); s_sq2 = fmaf(d, d, s_sq2);
    }

    // warp reduce
    #pragma unroll
    for (int off = 16; off > 0; off >>= 1) {
        s_abs1 += __shfl_down_sync(0xFFFFFFFF, s_abs1, off);
        s_abs2 += __shfl_down_sync(0xFFFFFFFF, s_abs2, off);
        s_sq1  += __shfl_down_sync(0xFFFFFFFF, s_sq1,  off);
        s_sq2  += __shfl_down_sync(0xFFFFFFFF, s_sq2,  off);
    }

    __shared__ float4 warp_sums[THREADS / 32];
    const int wid = tid >> 5;
    const int lid = tid & 31;
    if (lid == 0) warp_sums[wid] = make_float4(s_abs1, s_abs2, s_sq1, s_sq2);
    __syncthreads();

    if (wid == 0) {
        float4 v = (lid < THREADS / 32) ? warp_sums[lid]
                                        : make_float4(0.f, 0.f, 0.f, 0.f);
        #pragma unroll
        for (int off = (THREADS / 64); off > 0; off >>= 1) {
            v.x += __shfl_down_sync(0xFFFFFFFF, v.x, off);
            v.y += __shfl_down_sync(0xFFFFFFFF, v.y, off);
            v.z += __shfl_down_sync(0xFFFFFFFF, v.z, off);
            v.w += __shfl_down_sync(0xFFFFFFFF, v.w, off);
        }
        if (lid == 0) {
            const float l1_1 = v.x, l1_2 = v.y, sse1 = v.z, sse2 = v.w;
            const bool swap = (l1_1 >= l1_2);
            const float near_sse = swap ? sse2 : sse1;
            const float far_sse  = swap ? sse1 : sse2;
            const float la = label[b];
            const float l1 = label[i1];
            const float l2 = label[i2];
            const float near_label = swap ? l2 : l1;
            const float far_label  = swap ? l1 : l2;
            const float dfar  = la - far_label;
            const float dnear = la - near_label;
            const float alpha = dfar * dfar - dnear * dnear;
            const float loss = near_sse - far_sse + alpha * MARGIN;
            if (loss > 0.0f) atomicAdd(out, loss);
        }
    }
}

extern "C" void kernel_launch(void* const* d_in, const int* in_sizes, int n_in,
                              void* d_out, int out_size) {
    const float* feats = (const float*)d_in[0];
    const float* label = (const float*)d_in[1];
    const int*   idx1  = (const int*)d_in[2];
    const int*   idx2  = (const int*)d_in[3];
    float* out = (float*)d_out;

    zero_out_kernel<<<1, 1>>>(out);
    triplet_loss_kernel<<<B_CONST, THREADS>>>(feats, label, idx1, idx2, out);
}